// round 5
// baseline (speedup 1.0000x reference)
#include <cuda_runtime.h>
#include <cuda_bf16.h>

// Jones 4-pol congruence: V_p[a,d,n,t,f] = sum_{b,c} J[a,b,ant1[n],t,f] *
//                         V_m[b,c,n,t,f] * J[d,c,ant2[n],t,f]
// Layouts (row-major): V_m (2,2,NBL,T,F), jones (2,2,NANT,T,F), out (2,2,NBL,T,F)
// HBM/latency-bound streaming kernel.
// R2: L2 policy hints (.cs stream-once V_m/out, Jones L2-resident) -> 1.03 GB floor.
// R3 (FAILED): reg squeeze serialized loads -> MLP drop.
// R4 (WIN): 64-reg budget, 12 loads front-batched, 155.5us @ 84% DRAM.
// R5: 2 float4 groups per thread (same baseline, half-plane apart), all 24
//     loads front-batched under a 128-reg budget -> in-flight 330 -> 384/SM.

#define NPOL   2
#define NANT   64
#define NBL    2016
#define NTIMES 64
#define NFREQS 256

#define TF      (NTIMES * NFREQS)   // 16384
#define TF8     (TF / 8)            // 2048 thread-slots per baseline (2 groups each)
#define HALF    (TF / 2)            // 8192 element offset between the 2 groups
#define SPLANE  (NBL * TF)          // 33,030,144  (V_m / out plane stride)
#define SJPLANE (NANT * TF)         // 1,048,576   (jones plane stride)
#define NTHREADS_TOT (NBL * TF8)    // 4,128,768 threads

__device__ __forceinline__ float4 ldcs4(const float* p) {
    return __ldcs((const float4*)p);
}
__device__ __forceinline__ float4 ldg4(const float* p) {
    return __ldg((const float4*)p);
}
__device__ __forceinline__ void stcs4(float* p, float4 v) {
    __stcs((float4*)p, v);
}

__global__ __launch_bounds__(256, 2) void jones_congruence_kernel(
    const float* __restrict__ Vm,
    const float* __restrict__ J,
    const int*   __restrict__ ant1,
    const int*   __restrict__ ant2,
    float*       __restrict__ out)
{
    int idx = blockIdx.x * blockDim.x + threadIdx.x;
    if (idx >= NTHREADS_TOT) return;

    int n   = idx >> 11;                // baseline (TF8 = 2048 = 2^11)
    int tf  = (idx & (TF8 - 1)) << 2;   // group 0 element offset; group 1 at +HALF

    int base0 = n * TF + tf;
    int base1 = base0 + HALF;
    int a1 = __ldg(&ant1[n]);
    int a2 = __ldg(&ant2[n]);
    int jA0 = a1 * TF + tf,  jA1 = jA0 + HALF;
    int jB0 = a2 * TF + tf,  jB1 = jB0 + HALF;

    // ---- front-batch ALL 24 loads (deep MLP) ----
    // V_m planes (stream-once)
    float4 v00_0 = ldcs4(Vm + 0 * SPLANE + base0);
    float4 v01_0 = ldcs4(Vm + 1 * SPLANE + base0);
    float4 v10_0 = ldcs4(Vm + 2 * SPLANE + base0);
    float4 v11_0 = ldcs4(Vm + 3 * SPLANE + base0);
    float4 v00_1 = ldcs4(Vm + 0 * SPLANE + base1);
    float4 v01_1 = ldcs4(Vm + 1 * SPLANE + base1);
    float4 v10_1 = ldcs4(Vm + 2 * SPLANE + base1);
    float4 v11_1 = ldcs4(Vm + 3 * SPLANE + base1);

    // j1 planes (L2-resident)
    float4 a00_0 = ldg4(J + 0 * SJPLANE + jA0);
    float4 a01_0 = ldg4(J + 1 * SJPLANE + jA0);
    float4 a10_0 = ldg4(J + 2 * SJPLANE + jA0);
    float4 a11_0 = ldg4(J + 3 * SJPLANE + jA0);
    float4 a00_1 = ldg4(J + 0 * SJPLANE + jA1);
    float4 a01_1 = ldg4(J + 1 * SJPLANE + jA1);
    float4 a10_1 = ldg4(J + 2 * SJPLANE + jA1);
    float4 a11_1 = ldg4(J + 3 * SJPLANE + jA1);

    // j2 planes
    float4 b00_0 = ldg4(J + 0 * SJPLANE + jB0);
    float4 b01_0 = ldg4(J + 1 * SJPLANE + jB0);
    float4 b10_0 = ldg4(J + 2 * SJPLANE + jB0);
    float4 b11_0 = ldg4(J + 3 * SJPLANE + jB0);
    float4 b00_1 = ldg4(J + 0 * SJPLANE + jB1);
    float4 b01_1 = ldg4(J + 1 * SJPLANE + jB1);
    float4 b10_1 = ldg4(J + 2 * SJPLANE + jB1);
    float4 b11_1 = ldg4(J + 3 * SJPLANE + jB1);

    // M = J1 @ V ; O[a][d] = sum_c M[a][c] * J2[d][c]  (real -> conj = id)
#define JONES_LANE(g, s, o00, o01, o10, o11)                                 \
    {                                                                        \
        float m00 = a00_##g.s * v00_##g.s + a01_##g.s * v10_##g.s;           \
        float m01 = a00_##g.s * v01_##g.s + a01_##g.s * v11_##g.s;           \
        float m10 = a10_##g.s * v00_##g.s + a11_##g.s * v10_##g.s;           \
        float m11 = a10_##g.s * v01_##g.s + a11_##g.s * v11_##g.s;           \
        o00.s = m00 * b00_##g.s + m01 * b01_##g.s;                           \
        o01.s = m00 * b10_##g.s + m01 * b11_##g.s;                           \
        o10.s = m10 * b00_##g.s + m11 * b01_##g.s;                           \
        o11.s = m10 * b10_##g.s + m11 * b11_##g.s;                           \
    }

    // group 0: compute + store (frees its regs before group 1 results needed)
    {
        float4 o00, o01, o10, o11;
        JONES_LANE(0, x, o00, o01, o10, o11)
        JONES_LANE(0, y, o00, o01, o10, o11)
        JONES_LANE(0, z, o00, o01, o10, o11)
        JONES_LANE(0, w, o00, o01, o10, o11)
        stcs4(out + 0 * SPLANE + base0, o00);
        stcs4(out + 1 * SPLANE + base0, o01);
        stcs4(out + 2 * SPLANE + base0, o10);
        stcs4(out + 3 * SPLANE + base0, o11);
    }
    // group 1
    {
        float4 o00, o01, o10, o11;
        JONES_LANE(1, x, o00, o01, o10, o11)
        JONES_LANE(1, y, o00, o01, o10, o11)
        JONES_LANE(1, z, o00, o01, o10, o11)
        JONES_LANE(1, w, o00, o01, o10, o11)
        stcs4(out + 0 * SPLANE + base1, o00);
        stcs4(out + 1 * SPLANE + base1, o01);
        stcs4(out + 2 * SPLANE + base1, o10);
        stcs4(out + 3 * SPLANE + base1, o11);
    }
#undef JONES_LANE
}

extern "C" void kernel_launch(void* const* d_in, const int* in_sizes, int n_in,
                              void* d_out, int out_size)
{
    const float* Vm   = (const float*)d_in[0];
    const float* J    = (const float*)d_in[1];
    const int*   ant1 = (const int*)d_in[2];
    const int*   ant2 = (const int*)d_in[3];
    float*       out  = (float*)d_out;

    const int threads = 256;
    const int blocks  = (NTHREADS_TOT + threads - 1) / threads;  // 16128
    jones_congruence_kernel<<<blocks, threads>>>(Vm, J, ant1, ant2, out);
}